// round 3
// baseline (speedup 1.0000x reference)
#include <cuda_runtime.h>
#include <math.h>

// ---------------- problem constants ----------------
#define HH 8
#define DD 16
#define FF 128
#define F3 384
#define NLAYER 2
#define NTYPE 3
#define NREL 4
#define NTOT 80000
#define KRTOT 120000
#define ETOT 600000

// host-side metadata
static const int h_NS[3]    = {50000, 20000, 10000};
static const int h_OFFS[4]  = {0, 50000, 70000, 80000};
static const int h_ES[4]    = {300000, 150000, 100000, 50000};
static const int h_EBASE[4] = {0, 300000, 450000, 550000};
static const int h_SRCT[4]  = {0, 0, 2, 2};
static const int h_DSTT[4]  = {0, 1, 0, 1};
static const int h_KROFF[4] = {0, 50000, 100000, 110000};

// ---------------- device scratch (static, allocation-free) ----------------
__device__ float    g_x0[NTOT * FF];        // x at layer input (l=0)
__device__ float    g_x1[NTOT * FF];        // x at layer input (l=1)
__device__ float    g_kqv[NTOT * F3];       // [k | q | v] per node
__device__ float    g_kr[KRTOT * FF];       // relation-transformed k (per relation slab)
__device__ float    g_vr[KRTOT * FF];       // relation-transformed v
__device__ float    g_alpha[ETOT * HH];     // per-edge, per-head logits
__device__ unsigned g_amax[NTOT * HH];      // order-preserving-transformed max
__device__ float    g_denom[NTOT * HH];     // softmax denominator
__device__ float    g_agg[NTOT * FF];       // attention output per node
__device__ float    g_gelu[NTOT * FF];      // gelu(agg)

__device__ __forceinline__ float* sel_buf(int s) {
    if (s == 0) return g_x0;
    if (s == 1) return g_x1;
    if (s == 2) return g_gelu;
    return g_kqv;
}

// order-preserving float<->uint transform for atomicMax on floats
__device__ __forceinline__ unsigned f2o(float f) {
    unsigned u = __float_as_uint(f);
    return (u & 0x80000000u) ? ~u : (u | 0x80000000u);
}
__device__ __forceinline__ float o2f(unsigned t) {
    unsigned u = (t & 0x80000000u) ? (t ^ 0x80000000u) : ~t;
    return __uint_as_float(u);
}
#define AMAX_INIT 0x007FFFFFu  // f2o(-inf)

// ---------------- kernels ----------------

__global__ void copyin_kernel(const float* __restrict__ xg,
                              const float* __restrict__ xd,
                              const float* __restrict__ xr) {
    long i = (long)blockIdx.x * blockDim.x + threadIdx.x;
    if (i >= (long)NTOT * FF) return;
    const long n1 = 50000L * FF, n2 = 70000L * FF;
    float v;
    if (i < n1)      v = xg[i];
    else if (i < n2) v = xd[i - n1];
    else             v = xr[i - n2];
    g_x0[i] = v;
}

__global__ void init_kernel() {
    long i = (long)blockIdx.x * blockDim.x + threadIdx.x;
    if (i < (long)NTOT * HH) {
        g_amax[i] = AMAX_INIT;
        g_denom[i] = 0.f;
    }
    if (i < (long)NTOT * FF) g_agg[i] = 0.f;
}

// Generic fp32 GEMM: C[M,N] = A[M,128] @ B[128,N] + bias
// epi==1: out-layer epilogue: o -> s*o + (1-s)*x, relu(.)+x
__global__ __launch_bounds__(256)
void gemm_kernel(int a_sel, long a_off,
                 const float* __restrict__ B, const float* __restrict__ bias,
                 int c_sel, float* c_ext, long c_off,
                 int M, int N, int epi,
                 int x_sel, long x_off, const float* __restrict__ skipp) {
    __shared__ float As[32][65];
    __shared__ __align__(16) float Bs[32][64];
    const float* A = sel_buf(a_sel) + a_off;
    float* C = (c_sel >= 0 ? sel_buf(c_sel) : c_ext) + c_off;

    int tid = threadIdx.x;
    int tx = tid & 15, ty = tid >> 4;
    int bm = blockIdx.y * 64, bn = blockIdx.x * 64;

    float acc[4][4] = {};

    for (int k0 = 0; k0 < 128; k0 += 32) {
#pragma unroll
        for (int i = 0; i < 8; i++) {
            int e = tid + i * 256;
            int r = e >> 5, c = e & 31;
            int gr = bm + r;
            As[c][r] = (gr < M) ? A[(long)gr * 128 + k0 + c] : 0.f;
        }
#pragma unroll
        for (int i = 0; i < 8; i++) {
            int e = tid + i * 256;
            int r = e >> 6, c = e & 63;
            Bs[r][c] = B[(long)(k0 + r) * N + bn + c];
        }
        __syncthreads();
#pragma unroll
        for (int k = 0; k < 32; k++) {
            float4 b = *(const float4*)(&Bs[k][tx * 4]);
            float a_[4];
#pragma unroll
            for (int i = 0; i < 4; i++) a_[i] = As[k][ty * 4 + i];
#pragma unroll
            for (int i = 0; i < 4; i++) {
                acc[i][0] += a_[i] * b.x;
                acc[i][1] += a_[i] * b.y;
                acc[i][2] += a_[i] * b.z;
                acc[i][3] += a_[i] * b.w;
            }
        }
        __syncthreads();
    }

    float s = 0.f, oms = 0.f;
    const float* X = 0;
    if (epi) {
        float sv = *skipp;
        s = 1.f / (1.f + expf(-sv));
        oms = 1.f - s;
        X = sel_buf(x_sel) + x_off;
    }
    float4 bv = *(const float4*)&bias[bn + tx * 4];

#pragma unroll
    for (int i = 0; i < 4; i++) {
        int gr = bm + ty * 4 + i;
        if (gr >= M) continue;
        float o0 = acc[i][0] + bv.x;
        float o1 = acc[i][1] + bv.y;
        float o2 = acc[i][2] + bv.z;
        float o3 = acc[i][3] + bv.w;
        long base = (long)gr * N + bn + tx * 4;
        if (!epi) {
            float4 o4 = make_float4(o0, o1, o2, o3);
            *(float4*)&C[base] = o4;
        } else {
            float4 xv = *(const float4*)&X[(long)gr * 128 + bn + tx * 4];
            float n0 = s * o0 + oms * xv.x;
            float n1 = s * o1 + oms * xv.y;
            float n2 = s * o2 + oms * xv.z;
            float n3 = s * o3 + oms * xv.w;
            float4 r4 = make_float4(fmaxf(n0, 0.f) + xv.x, fmaxf(n1, 0.f) + xv.y,
                                    fmaxf(n2, 0.f) + xv.z, fmaxf(n3, 0.f) + xv.w);
            *(float4*)&C[base] = r4;
        }
    }
}

// k_r = einsum('nhd,hde->nhe', k, Ak[r]); v_r likewise. 16 nodes/block.
__global__ __launch_bounds__(256)
void krvr_kernel(const float* __restrict__ Ak, const float* __restrict__ Av,
                 int l, int r, int st_off, int nsrc, int kroff) {
    __shared__ float sA[2][HH][DD][DD];  // [k/v][h][d][e] : 16 KB
    int tid = threadIdx.x;
    const float* Akb = Ak + (long)(l * NREL + r) * HH * DD * DD;
    const float* Avb = Av + (long)(l * NREL + r) * HH * DD * DD;
    float* sflat = &sA[0][0][0][0];
    for (int i = tid; i < 2048; i += 256) {
        sflat[i] = Akb[i];
        sflat[2048 + i] = Avb[i];
    }
    __syncthreads();

    int half = tid >> 7;           // 0 = k, 1 = v
    int h = (tid & 127) >> 4;
    int e = tid & 15;
    int n0 = blockIdx.x * 16;
    float* dst = half ? g_vr : g_kr;
    int kqv_off = half ? 256 : 0;  // k at [0:128), v at [256:384)

    for (int ni = 0; ni < 16; ni++) {
        int n = n0 + ni;
        if (n >= nsrc) break;
        const float* srcp = g_kqv + (long)(st_off + n) * F3 + kqv_off + h * DD;
        float acc = 0.f;
#pragma unroll
        for (int d = 0; d < DD; d++) acc += srcp[d] * sA[half][h][d][e];
        dst[(long)(kroff + n) * FF + h * DD + e] = acc;
    }
}

// one warp per edge: alpha logits + atomicMax into g_amax
__global__ __launch_bounds__(256)
void alpha_kernel(const int* __restrict__ src, const int* __restrict__ dst,
                  const float* __restrict__ prel,
                  int E, int l, int r, int dt_off, int kroff, int ebase) {
    int warp = (blockIdx.x * blockDim.x + threadIdx.x) >> 5;
    int lane = threadIdx.x & 31;
    if (warp >= E) return;
    int sn = src[warp], dn = dst[warp];
    float4 q4 = *(const float4*)(g_kqv + (long)(dt_off + dn) * F3 + FF + lane * 4);
    float4 k4 = *(const float4*)(g_kr + (long)(kroff + sn) * FF + lane * 4);
    float p = q4.x * k4.x + q4.y * k4.y + q4.z * k4.z + q4.w * k4.w;
    p += __shfl_xor_sync(0xFFFFFFFFu, p, 1);
    p += __shfl_xor_sync(0xFFFFFFFFu, p, 2);
    if ((lane & 3) == 0) {
        int h = lane >> 2;
        float a = p * prel[(l * NREL + r) * HH + h] * 0.25f;  // 1/sqrt(16)
        g_alpha[(long)(ebase + warp) * HH + h] = a;
        atomicMax(&g_amax[(long)(dt_off + dn) * HH + h], f2o(a));
    }
}

// one thread per (edge, head): accumulate softmax denominator
__global__ __launch_bounds__(256)
void denom_kernel(const int* __restrict__ dst, int E, int dt_off, int ebase) {
    long idx = (long)blockIdx.x * blockDim.x + threadIdx.x;
    if (idx >= (long)E * HH) return;
    int e = (int)(idx >> 3), h = (int)(idx & 7);
    int dn = dst[e];
    float a = g_alpha[(long)(ebase + e) * HH + h];
    float m = o2f(g_amax[(long)(dt_off + dn) * HH + h]);
    atomicAdd(&g_denom[(long)(dt_off + dn) * HH + h], expf(a - m));
}

// one warp per edge: out[dst] += v_r[src] * softmax_weight
__global__ __launch_bounds__(256)
void agg_kernel(const int* __restrict__ src, const int* __restrict__ dst,
                int E, int dt_off, int kroff, int ebase) {
    int warp = (blockIdx.x * blockDim.x + threadIdx.x) >> 5;
    int lane = threadIdx.x & 31;
    if (warp >= E) return;
    int sn = src[warp], dn = dst[warp];
    int h = lane >> 2;
    long nb = (long)(dt_off + dn) * HH + h;
    float a = g_alpha[(long)(ebase + warp) * HH + h];
    float m = o2f(g_amax[nb]);
    float den = g_denom[nb];
    float w = expf(a - m) / den;
    float4 v4 = *(const float4*)(g_vr + (long)(kroff + sn) * FF + lane * 4);
    float* o = g_agg + (long)(dt_off + dn) * FF + lane * 4;
    atomicAdd(o + 0, v4.x * w);
    atomicAdd(o + 1, v4.y * w);
    atomicAdd(o + 2, v4.z * w);
    atomicAdd(o + 3, v4.w * w);
}

__global__ void gelu_kernel() {
    long i = (long)blockIdx.x * blockDim.x + threadIdx.x;
    if (i >= (long)NTOT * FF) return;
    float x = g_agg[i];
    g_gelu[i] = 0.5f * x * (1.f + erff(x * 0.70710678118654752440f));
}

// ---------------- launch ----------------
extern "C" void kernel_launch(void* const* d_in, const int* in_sizes, int n_in,
                              void* d_out, int out_size) {
    const float* xg   = (const float*)d_in[0];
    const float* xd   = (const float*)d_in[1];
    const float* xr   = (const float*)d_in[2];
    const float* Wkqv = (const float*)d_in[3];
    const float* bkqv = (const float*)d_in[4];
    const float* Ak   = (const float*)d_in[5];
    const float* Av   = (const float*)d_in[6];
    const float* prel = (const float*)d_in[7];
    const float* Wout = (const float*)d_in[8];
    const float* bout = (const float*)d_in[9];
    const float* skip = (const float*)d_in[10];
    const int* ei[4] = {(const int*)d_in[11], (const int*)d_in[12],
                        (const int*)d_in[13], (const int*)d_in[14]};
    float* outp = (float*)d_out;

    const int NELEM_BLOCKS = (NTOT * FF + 255) / 256;  // 40000

    copyin_kernel<<<NELEM_BLOCKS, 256>>>(xg, xd, xr);

    for (int l = 0; l < NLAYER; l++) {
        int a_x = (l == 0) ? 0 : 1;  // selector for current-x buffer

        // 1) kqv = x @ Wkqv + bkqv  per type
        for (int t = 0; t < NTYPE; t++) {
            dim3 grid(F3 / 64, (h_NS[t] + 63) / 64);
            gemm_kernel<<<grid, 256>>>(
                a_x, (long)h_OFFS[t] * FF,
                Wkqv + (long)(l * NTYPE + t) * FF * F3,
                bkqv + (long)(l * NTYPE + t) * F3,
                3 /*g_kqv*/, 0, (long)h_OFFS[t] * F3,
                h_NS[t], F3, 0, 0, 0, 0);
        }

        // 2) reset softmax/aggregation state
        init_kernel<<<NELEM_BLOCKS, 256>>>();

        // 3) relation-specific k_r, v_r
        for (int r = 0; r < NREL; r++) {
            int st = h_SRCT[r];
            krvr_kernel<<<(h_NS[st] + 15) / 16, 256>>>(
                Ak, Av, l, r, h_OFFS[st], h_NS[st], h_KROFF[r]);
        }

        // 4) edge logits + segment max
        for (int r = 0; r < NREL; r++) {
            int E = h_ES[r];
            alpha_kernel<<<(E * 32 + 255) / 256, 256>>>(
                ei[r], ei[r] + E, prel, E, l, r,
                h_OFFS[h_DSTT[r]], h_KROFF[r], h_EBASE[r]);
        }

        // 5) softmax denominators
        for (int r = 0; r < NREL; r++) {
            int E = h_ES[r];
            denom_kernel<<<(E * HH + 255) / 256, 256>>>(
                ei[r] + E, E, h_OFFS[h_DSTT[r]], h_EBASE[r]);
        }

        // 6) weighted scatter-add of v_r
        for (int r = 0; r < NREL; r++) {
            int E = h_ES[r];
            agg_kernel<<<(E * 32 + 255) / 256, 256>>>(
                ei[r], ei[r] + E, E,
                h_OFFS[h_DSTT[r]], h_KROFF[r], h_EBASE[r]);
        }

        // 7) gelu
        gelu_kernel<<<NELEM_BLOCKS, 256>>>();

        // 8) out GEMM + skip-blend + relu + residual  (last layer -> d_out)
        for (int t = 0; t < NTYPE; t++) {
            dim3 grid(FF / 64, (h_NS[t] + 63) / 64);
            int c_sel = (l == 0) ? 1 : -1;
            gemm_kernel<<<grid, 256>>>(
                2 /*g_gelu*/, (long)h_OFFS[t] * FF,
                Wout + (long)(l * NTYPE + t) * FF * FF,
                bout + (long)(l * NTYPE + t) * FF,
                c_sel, outp, (long)h_OFFS[t] * FF,
                h_NS[t], FF, 1,
                a_x, (long)h_OFFS[t] * FF,
                skip + l * NTYPE + t);
        }
    }
    (void)in_sizes; (void)n_in; (void)out_size;
}

// round 5
// speedup vs baseline: 1.1527x; 1.1527x over previous
#include <cuda_runtime.h>
#include <math.h>

// ---------------- problem constants ----------------
#define HH 8
#define DD 16
#define FF 128
#define F3 384
#define NLAYER 2
#define NTYPE 3
#define NREL 4
#define NTOT 80000
#define KRTOT 120000
#define ETOT 600000

// host-side metadata
static const int h_NS[3]    = {50000, 20000, 10000};
static const int h_OFFS[4]  = {0, 50000, 70000, 80000};
static const int h_ES[4]    = {300000, 150000, 100000, 50000};
static const int h_EBASE[4] = {0, 300000, 450000, 550000};
static const int h_SRCT[4]  = {0, 0, 2, 2};
static const int h_DSTT[4]  = {0, 1, 0, 1};
static const int h_KROFF[4] = {0, 50000, 100000, 110000};

// ---------------- device scratch (static, allocation-free) ----------------
__device__ __align__(16) float g_x0[NTOT * FF];
__device__ __align__(16) float g_x1[NTOT * FF];
__device__ __align__(16) float g_kqv[NTOT * F3];
__device__ __align__(16) float g_kr[KRTOT * FF];
__device__ __align__(16) float g_vr[KRTOT * FF];
__device__ __align__(16) float g_alpha[ETOT * HH];   // holds exp(logit)
__device__ __align__(16) float g_denom[NTOT * HH];
__device__ __align__(16) float g_agg[NTOT * FF];

__device__ __forceinline__ float* sel_buf(int s) {
    if (s == 0) return g_x0;
    if (s == 1) return g_x1;
    if (s == 2) return g_agg;
    return g_kqv;
}

// ---------------- kernels ----------------

__global__ void copyin_kernel(const float* __restrict__ xg,
                              const float* __restrict__ xd,
                              const float* __restrict__ xr) {
    long i = (long)blockIdx.x * blockDim.x + threadIdx.x;
    if (i >= (long)NTOT * FF) return;
    const long n1 = 50000L * FF, n2 = 70000L * FF;
    float v;
    if (i < n1)      v = xg[i];
    else if (i < n2) v = xd[i - n1];
    else             v = xr[i - n2];
    g_x0[i] = v;
}

__global__ void init_kernel() {
    long i = (long)blockIdx.x * blockDim.x + threadIdx.x;
    if (i < (long)NTOT * HH) g_denom[i] = 0.f;
    if (i < (long)NTOT * FF) g_agg[i] = 0.f;
}

__device__ __forceinline__ float gelu_f(float x) {
    return 0.5f * x * (1.f + erff(x * 0.70710678118654752440f));
}

// fp32 GEMM: C[M,N] = act(A[M,128]) @ B[128,N] + bias
// 128x128 block tile, 16 k-chunk, 8x8 per-thread micro-tile, 256 threads.
// act==1: gelu applied to A elements on load.
// epi==1: o -> s*o + (1-s)*x ; out = relu(.) + x   (skip blend + residual)
__global__ __launch_bounds__(256, 2)
void gemm_kernel(int a_sel, long a_off,
                 const float* __restrict__ B, const float* __restrict__ bias,
                 int c_sel, float* c_ext, long c_off,
                 int M, int N, int act, int epi,
                 int x_sel, long x_off, const float* __restrict__ skipp) {
    __shared__ float As[16][132];                 // [k][m], padded
    __shared__ __align__(16) float Bs[16][128];   // [k][n]
    const float* A = sel_buf(a_sel) + a_off;
    float* C = (c_sel >= 0 ? sel_buf(c_sel) : c_ext) + c_off;

    int t  = threadIdx.x;
    int bm = blockIdx.y * 128, bn = blockIdx.x * 128;
    int ty = t >> 4, tx = t & 15;
    int m0 = ty * 8, n0 = tx * 8;

    float acc[8][8] = {};

    for (int k0 = 0; k0 < 128; k0 += 16) {
        // A tile: 128 rows x 16 cols -> transposed into As
#pragma unroll
        for (int i = 0; i < 2; i++) {
            int id  = t + i * 256;
            int row = id >> 2, cg = id & 3;
            float4 v = make_float4(0.f, 0.f, 0.f, 0.f);
            if (bm + row < M)
                v = *(const float4*)&A[(long)(bm + row) * 128 + k0 + cg * 4];
            if (act) {
                v.x = gelu_f(v.x); v.y = gelu_f(v.y);
                v.z = gelu_f(v.z); v.w = gelu_f(v.w);
            }
            As[cg * 4 + 0][row] = v.x;
            As[cg * 4 + 1][row] = v.y;
            As[cg * 4 + 2][row] = v.z;
            As[cg * 4 + 3][row] = v.w;
        }
        // B tile: 16 rows x 128 cols
#pragma unroll
        for (int i = 0; i < 2; i++) {
            int id  = t + i * 256;
            int row = id >> 5, c4 = id & 31;
            *(float4*)&Bs[row][c4 * 4] =
                *(const float4*)&B[(long)(k0 + row) * N + bn + c4 * 4];
        }
        __syncthreads();

#pragma unroll
        for (int k = 0; k < 16; k++) {
            float4 a0 = *(const float4*)&As[k][m0];
            float4 a1 = *(const float4*)&As[k][m0 + 4];
            float4 b0 = *(const float4*)&Bs[k][n0];
            float4 b1 = *(const float4*)&Bs[k][n0 + 4];
            float av[8] = {a0.x, a0.y, a0.z, a0.w, a1.x, a1.y, a1.z, a1.w};
            float bv[8] = {b0.x, b0.y, b0.z, b0.w, b1.x, b1.y, b1.z, b1.w};
#pragma unroll
            for (int i = 0; i < 8; i++)
#pragma unroll
                for (int j = 0; j < 8; j++)
                    acc[i][j] += av[i] * bv[j];
        }
        __syncthreads();
    }

    float s = 0.f, oms = 0.f;
    const float* X = 0;
    if (epi) {
        float sv = *skipp;
        s = 1.f / (1.f + expf(-sv));
        oms = 1.f - s;
        X = sel_buf(x_sel) + x_off;
    }
    float4 bv0 = *(const float4*)&bias[bn + n0];
    float4 bv1 = *(const float4*)&bias[bn + n0 + 4];
    float bb[8] = {bv0.x, bv0.y, bv0.z, bv0.w, bv1.x, bv1.y, bv1.z, bv1.w};

#pragma unroll
    for (int i = 0; i < 8; i++) {
        int gr = bm + m0 + i;
        if (gr >= M) continue;
        float o[8];
#pragma unroll
        for (int j = 0; j < 8; j++) o[j] = acc[i][j] + bb[j];
        long base = (long)gr * N + bn + n0;
        if (!epi) {
            *(float4*)&C[base]     = make_float4(o[0], o[1], o[2], o[3]);
            *(float4*)&C[base + 4] = make_float4(o[4], o[5], o[6], o[7]);
        } else {
            float4 xv0 = *(const float4*)&X[(long)gr * 128 + bn + n0];
            float4 xv1 = *(const float4*)&X[(long)gr * 128 + bn + n0 + 4];
            float xx[8] = {xv0.x, xv0.y, xv0.z, xv0.w, xv1.x, xv1.y, xv1.z, xv1.w};
            float r[8];
#pragma unroll
            for (int j = 0; j < 8; j++) {
                float n = s * o[j] + oms * xx[j];
                r[j] = fmaxf(n, 0.f) + xx[j];
            }
            *(float4*)&C[base]     = make_float4(r[0], r[1], r[2], r[3]);
            *(float4*)&C[base + 4] = make_float4(r[4], r[5], r[6], r[7]);
        }
    }
}

// k_r = einsum('nhd,hde->nhe', k, Ak[r]); v_r likewise. 16 nodes/block.
__global__ __launch_bounds__(256)
void krvr_kernel(const float* __restrict__ Ak, const float* __restrict__ Av,
                 int l, int r, int st_off, int nsrc, int kroff) {
    __shared__ float sA[2][HH][DD][DD];  // [k/v][h][d][e] : 16 KB
    int tid = threadIdx.x;
    const float* Akb = Ak + (long)(l * NREL + r) * HH * DD * DD;
    const float* Avb = Av + (long)(l * NREL + r) * HH * DD * DD;
    float* sflat = &sA[0][0][0][0];
    for (int i = tid; i < 2048; i += 256) {
        sflat[i] = Akb[i];
        sflat[2048 + i] = Avb[i];
    }
    __syncthreads();

    int half = tid >> 7;           // 0 = k, 1 = v
    int h = (tid & 127) >> 4;
    int e = tid & 15;
    int n0 = blockIdx.x * 16;
    float* dst = half ? g_vr : g_kr;
    int kqv_off = half ? 256 : 0;  // k at [0:128), v at [256:384)

    for (int ni = 0; ni < 16; ni++) {
        int n = n0 + ni;
        if (n >= nsrc) break;
        const float* srcp = g_kqv + (long)(st_off + n) * F3 + kqv_off + h * DD;
        float acc = 0.f;
#pragma unroll
        for (int d = 0; d < DD; d++) acc += srcp[d] * sA[half][h][d][e];
        dst[(long)(kroff + n) * FF + h * DD + e] = acc;
    }
}

// one warp per edge: attention logits -> exp -> denominator accumulation
// (segment-max is skipped: logits are O(1), exp cannot overflow; softmax
//  weights exp(a)/sum(exp(a)) are mathematically identical without the max)
__global__ __launch_bounds__(256)
void alpha_kernel(const int* __restrict__ src, const int* __restrict__ dst,
                  const float* __restrict__ prel,
                  int E, int l, int r, int dt_off, int kroff, int ebase) {
    int warp = (blockIdx.x * blockDim.x + threadIdx.x) >> 5;
    int lane = threadIdx.x & 31;
    if (warp >= E) return;
    int sn = src[warp], dn = dst[warp];
    float4 q4 = *(const float4*)(g_kqv + (long)(dt_off + dn) * F3 + FF + lane * 4);
    float4 k4 = *(const float4*)(g_kr + (long)(kroff + sn) * FF + lane * 4);
    float p = q4.x * k4.x + q4.y * k4.y + q4.z * k4.z + q4.w * k4.w;
    p += __shfl_xor_sync(0xFFFFFFFFu, p, 1);
    p += __shfl_xor_sync(0xFFFFFFFFu, p, 2);
    if ((lane & 3) == 0) {
        int h = lane >> 2;
        float a = p * prel[(l * NREL + r) * HH + h] * 0.25f;  // 1/sqrt(16)
        float ex = expf(a);
        g_alpha[(long)(ebase + warp) * HH + h] = ex;
        atomicAdd(&g_denom[(long)(dt_off + dn) * HH + h], ex);
    }
}

// one warp per edge: out[dst] += v_r[src] * softmax_weight (vector RED)
__global__ __launch_bounds__(256)
void agg_kernel(const int* __restrict__ src, const int* __restrict__ dst,
                int E, int dt_off, int kroff, int ebase) {
    int warp = (blockIdx.x * blockDim.x + threadIdx.x) >> 5;
    int lane = threadIdx.x & 31;
    if (warp >= E) return;
    int sn = src[warp], dn = dst[warp];
    int h = lane >> 2;
    long nb = (long)(dt_off + dn) * HH + h;
    float ex  = g_alpha[(long)(ebase + warp) * HH + h];
    float den = g_denom[nb];
    float w = ex / den;
    float4 v4 = *(const float4*)(g_vr + (long)(kroff + sn) * FF + lane * 4);
    float* o = g_agg + (long)(dt_off + dn) * FF + lane * 4;
    asm volatile("red.global.add.v4.f32 [%0], {%1,%2,%3,%4};"
                 :: "l"(o), "f"(v4.x * w), "f"(v4.y * w),
                    "f"(v4.z * w), "f"(v4.w * w)
                 : "memory");
}

// ---------------- launch ----------------
extern "C" void kernel_launch(void* const* d_in, const int* in_sizes, int n_in,
                              void* d_out, int out_size) {
    const float* xg   = (const float*)d_in[0];
    const float* xd   = (const float*)d_in[1];
    const float* xr   = (const float*)d_in[2];
    const float* Wkqv = (const float*)d_in[3];
    const float* bkqv = (const float*)d_in[4];
    const float* Ak   = (const float*)d_in[5];
    const float* Av   = (const float*)d_in[6];
    const float* prel = (const float*)d_in[7];
    const float* Wout = (const float*)d_in[8];
    const float* bout = (const float*)d_in[9];
    const float* skip = (const float*)d_in[10];
    const int* ei[4] = {(const int*)d_in[11], (const int*)d_in[12],
                        (const int*)d_in[13], (const int*)d_in[14]};
    float* outp = (float*)d_out;

    const int NELEM_BLOCKS = (NTOT * FF + 255) / 256;  // 40000

    copyin_kernel<<<NELEM_BLOCKS, 256>>>(xg, xd, xr);

    for (int l = 0; l < NLAYER; l++) {
        int a_x = (l == 0) ? 0 : 1;  // selector for current-x buffer

        // 1) kqv = x @ Wkqv + bkqv  per type
        for (int t = 0; t < NTYPE; t++) {
            dim3 grid(F3 / 128, (h_NS[t] + 127) / 128);
            gemm_kernel<<<grid, 256>>>(
                a_x, (long)h_OFFS[t] * FF,
                Wkqv + (long)(l * NTYPE + t) * FF * F3,
                bkqv + (long)(l * NTYPE + t) * F3,
                3 /*g_kqv*/, 0, (long)h_OFFS[t] * F3,
                h_NS[t], F3, 0, 0, 0, 0, 0);
        }

        // 2) reset softmax/aggregation state
        init_kernel<<<NELEM_BLOCKS, 256>>>();

        // 3) relation-specific k_r, v_r
        for (int r = 0; r < NREL; r++) {
            int st = h_SRCT[r];
            krvr_kernel<<<(h_NS[st] + 15) / 16, 256>>>(
                Ak, Av, l, r, h_OFFS[st], h_NS[st], h_KROFF[r]);
        }

        // 4) edge logits + exp + denominator (fused; no segment-max)
        for (int r = 0; r < NREL; r++) {
            int E = h_ES[r];
            alpha_kernel<<<(E * 32 + 255) / 256, 256>>>(
                ei[r], ei[r] + E, prel, E, l, r,
                h_OFFS[h_DSTT[r]], h_KROFF[r], h_EBASE[r]);
        }

        // 5) weighted scatter-add of v_r (vector RED)
        for (int r = 0; r < NREL; r++) {
            int E = h_ES[r];
            agg_kernel<<<(E * 32 + 255) / 256, 256>>>(
                ei[r], ei[r] + E, E,
                h_OFFS[h_DSTT[r]], h_KROFF[r], h_EBASE[r]);
        }

        // 6) out GEMM + gelu(A) + skip-blend + relu + residual
        for (int t = 0; t < NTYPE; t++) {
            dim3 grid(FF / 128, (h_NS[t] + 127) / 128);
            int c_sel = (l == 0) ? 1 : -1;
            gemm_kernel<<<grid, 256>>>(
                2 /*g_agg*/, (long)h_OFFS[t] * FF,
                Wout + (long)(l * NTYPE + t) * FF * FF,
                bout + (long)(l * NTYPE + t) * FF,
                c_sel, outp, (long)h_OFFS[t] * FF,
                h_NS[t], FF, 1 /*act*/, 1 /*epi*/,
                a_x, (long)h_OFFS[t] * FF,
                skip + l * NTYPE + t);
        }
    }
    (void)in_sizes; (void)n_in; (void)out_size;
}

// round 6
// speedup vs baseline: 1.4123x; 1.2253x over previous
#include <cuda_runtime.h>
#include <cuda_bf16.h>
#include <math.h>

// ---------------- problem constants ----------------
#define HH 8
#define DD 16
#define FF 128
#define F3 384
#define NLAYER 2
#define NTYPE 3
#define NREL 4
#define NTOT 80000
#define KRTOT 120000
#define ETOT 600000
#define BKPAD 40           // smem k-stride in bf16 (80 bytes): conflict-free ldmatrix

#define KQVW_ELEMS (NLAYER * NTYPE * F3 * FF)   // 294912
#define OUTW_ELEMS (NLAYER * NTYPE * FF * FF)   //  98304
#define WTOT (KQVW_ELEMS + OUTW_ELEMS)

// host-side metadata
static const int h_NS[3]    = {50000, 20000, 10000};
static const int h_OFFS[4]  = {0, 50000, 70000, 80000};
static const int h_ES[4]    = {300000, 150000, 100000, 50000};
static const int h_EBASE[4] = {0, 300000, 450000, 550000};
static const int h_SRCT[4]  = {0, 0, 2, 2};
static const int h_DSTT[4]  = {0, 1, 0, 1};
static const int h_KROFF[4] = {0, 50000, 100000, 110000};

// ---------------- device scratch ----------------
__device__ __align__(16) float g_x0[NTOT * FF];
__device__ __align__(16) float g_x1[NTOT * FF];
__device__ __align__(16) float g_kqv[NTOT * F3];
__device__ __align__(16) float g_kr[KRTOT * FF];
__device__ __align__(16) float g_vr[KRTOT * FF];
__device__ __align__(16) float g_alpha[ETOT * HH];
__device__ __align__(16) float g_denom[NTOT * HH];
__device__ __align__(16) float g_agg[NTOT * FF];
// bf16x2 split planes
__device__ __align__(16) __nv_bfloat16 g_ah[NTOT * FF];
__device__ __align__(16) __nv_bfloat16 g_al[NTOT * FF];
__device__ __align__(16) __nv_bfloat16 g_wh[WTOT];   // weights, [n][k] k-major
__device__ __align__(16) __nv_bfloat16 g_wl[WTOT];

__device__ __forceinline__ float* sel_buf(int s) {
    if (s == 0) return g_x0;
    if (s == 1) return g_x1;
    if (s == 2) return g_agg;
    return g_kqv;
}

__device__ __forceinline__ float gelu_f(float x) {
    return 0.5f * x * (1.f + erff(x * 0.70710678118654752440f));
}

// ---------------- utility kernels ----------------

__global__ void copyin_kernel(const float* __restrict__ xg,
                              const float* __restrict__ xd,
                              const float* __restrict__ xr) {
    long i = (long)blockIdx.x * blockDim.x + threadIdx.x;
    if (i >= (long)NTOT * FF) return;
    const long n1 = 50000L * FF, n2 = 70000L * FF;
    float v;
    if (i < n1)      v = xg[i];
    else if (i < n2) v = xd[i - n1];
    else             v = xr[i - n2];
    g_x0[i] = v;
}

__global__ void init_kernel() {
    long i = (long)blockIdx.x * blockDim.x + threadIdx.x;
    if (i < (long)NTOT * HH) g_denom[i] = 0.f;
    if (i < (long)NTOT * FF) g_agg[i] = 0.f;
}

// split weights into transposed (k-major) bf16 hi/lo planes. Runs once per call.
__global__ void splitw_kernel(const float* __restrict__ Wkqv,
                              const float* __restrict__ Wout) {
    int idx = blockIdx.x * blockDim.x + threadIdx.x;
    if (idx >= WTOT) return;
    float val;
    if (idx < KQVW_ELEMS) {
        int lt = idx / (F3 * FF);
        int rem = idx - lt * (F3 * FF);
        int n = rem / FF, k = rem % FF;
        val = Wkqv[(long)lt * FF * F3 + (long)k * F3 + n];
    } else {
        int j = idx - KQVW_ELEMS;
        int lt = j / (FF * FF);
        int rem = j - lt * (FF * FF);
        int n = rem / FF, k = rem % FF;
        val = Wout[(long)lt * FF * FF + (long)k * FF + n];
    }
    __nv_bfloat16 hi = __float2bfloat16_rn(val);
    __nv_bfloat16 lo = __float2bfloat16_rn(val - __bfloat162float(hi));
    g_wh[idx] = hi;
    g_wl[idx] = lo;
}

// split activations (optionally gelu) into bf16 hi/lo planes, 8 elems/thread
__global__ void split_kernel(int src_sel, int act) {
    long i8 = ((long)blockIdx.x * blockDim.x + threadIdx.x) * 8;
    if (i8 >= (long)NTOT * FF) return;
    const float* s = sel_buf(src_sel);
    float v[8];
    *(float4*)&v[0] = *(const float4*)&s[i8];
    *(float4*)&v[4] = *(const float4*)&s[i8 + 4];
    __nv_bfloat16 h[8], l[8];
#pragma unroll
    for (int j = 0; j < 8; j++) {
        float x = act ? gelu_f(v[j]) : v[j];
        h[j] = __float2bfloat16_rn(x);
        l[j] = __float2bfloat16_rn(x - __bfloat162float(h[j]));
    }
    *(uint4*)&g_ah[i8] = *(const uint4*)&h[0];
    *(uint4*)&g_al[i8] = *(const uint4*)&l[0];
}

// ---------------- tensor-core GEMM ----------------
// C[M,N] = A[M,128] @ B[128,N] + bias, via bf16x2 split (Ah Bh + Ah Bl + Al Bh)
// A planes: g_ah/g_al rows [a_row_off + m].  B planes: g_wh/g_wl + b_off, [n][128].
// epi==1: o -> s*o+(1-s)*x ; out = relu(.)+x
#define LDSM4(r, addr) \
    asm volatile("ldmatrix.sync.aligned.m8n8.x4.shared.b16 {%0,%1,%2,%3}, [%4];" \
        : "=r"((r)[0]), "=r"((r)[1]), "=r"((r)[2]), "=r"((r)[3]) : "r"(addr))

#define MMA16816(c, a0, a1, a2, a3, b0, b1) \
    asm volatile("mma.sync.aligned.m16n8k16.row.col.f32.bf16.bf16.f32 " \
        "{%0,%1,%2,%3}, {%4,%5,%6,%7}, {%8,%9}, {%0,%1,%2,%3};" \
        : "+f"((c)[0]), "+f"((c)[1]), "+f"((c)[2]), "+f"((c)[3]) \
        : "r"(a0), "r"(a1), "r"(a2), "r"(a3), "r"(b0), "r"(b1))

__global__ __launch_bounds__(256)
void mma_gemm(long a_row_off, long b_off, const float* __restrict__ bias,
              int c_sel, float* c_ext, long c_off,
              int M, int N, int epi,
              int x_sel, long x_off, const float* __restrict__ skipp) {
    __shared__ __align__(16) __nv_bfloat16 sAh[128 * BKPAD];
    __shared__ __align__(16) __nv_bfloat16 sAl[128 * BKPAD];
    __shared__ __align__(16) __nv_bfloat16 sBh[128 * BKPAD];
    __shared__ __align__(16) __nv_bfloat16 sBl[128 * BKPAD];

    int t = threadIdx.x;
    int bm = blockIdx.y * 128, bn = blockIdx.x * 128;
    int lane = t & 31, wid = t >> 5;
    int wm = (wid & 1) * 64, wn = (wid >> 1) * 32;

    float* C = (c_sel >= 0 ? sel_buf(c_sel) : c_ext) + c_off;

    float acc[4][4][4];
#pragma unroll
    for (int a = 0; a < 4; a++)
#pragma unroll
        for (int b = 0; b < 4; b++)
#pragma unroll
            for (int c = 0; c < 4; c++) acc[a][b][c] = 0.f;

    for (int kc = 0; kc < 128; kc += 32) {
        // ---- stage A (128 rows x 32 k, 2 planes) ----
#pragma unroll
        for (int i = 0; i < 4; i++) {
            int id = t + i * 256;
            int j = id & 3, m = (id >> 2) & 127, pl = id >> 9;
            const __nv_bfloat16* src = pl ? g_al : g_ah;
            __nv_bfloat16* dstS = pl ? sAl : sAh;
            uint4 v = make_uint4(0u, 0u, 0u, 0u);
            int gr = bm + m;
            if (gr < M)
                v = *(const uint4*)(src + (a_row_off + gr) * 128 + kc + j * 8);
            *(uint4*)(dstS + m * BKPAD + j * 8) = v;
        }
        // ---- stage B (128 n-rows x 32 k, 2 planes) ----
#pragma unroll
        for (int i = 0; i < 4; i++) {
            int id = t + i * 256;
            int j = id & 3, n = (id >> 2) & 127, pl = id >> 9;
            const __nv_bfloat16* src = pl ? g_wl : g_wh;
            __nv_bfloat16* dstS = pl ? sBl : sBh;
            uint4 v = *(const uint4*)(src + b_off + (long)(bn + n) * 128 + kc + j * 8);
            *(uint4*)(dstS + n * BKPAD + j * 8) = v;
        }
        __syncthreads();

#pragma unroll
        for (int k16 = 0; k16 < 32; k16 += 16) {
            // A fragments: 4 m-tiles x {hi,lo}
            unsigned af[4][2][4];
            int arow = wm + (lane & 15);
            int akoff = k16 + (lane >> 4) * 8;
#pragma unroll
            for (int mi = 0; mi < 4; mi++) {
                unsigned ah = (unsigned)__cvta_generic_to_shared(
                    sAh + (arow + mi * 16) * BKPAD + akoff);
                unsigned al = (unsigned)__cvta_generic_to_shared(
                    sAl + (arow + mi * 16) * BKPAD + akoff);
                LDSM4(af[mi][0], ah);
                LDSM4(af[mi][1], al);
            }
#pragma unroll
            for (int p = 0; p < 2; p++) {
                int nrow = wn + p * 16 + ((lane >> 4) & 1) * 8 + (lane & 7);
                int bkoff = k16 + ((lane >> 3) & 1) * 8;
                unsigned bh[4], bl[4];
                unsigned bha = (unsigned)__cvta_generic_to_shared(
                    sBh + nrow * BKPAD + bkoff);
                unsigned bla = (unsigned)__cvta_generic_to_shared(
                    sBl + nrow * BKPAD + bkoff);
                LDSM4(bh, bha);
                LDSM4(bl, bla);
#pragma unroll
                for (int mi = 0; mi < 4; mi++) {
                    // n-tile 2p
                    MMA16816(acc[mi][2 * p], af[mi][0][0], af[mi][0][1], af[mi][0][2], af[mi][0][3], bh[0], bh[1]);
                    MMA16816(acc[mi][2 * p], af[mi][0][0], af[mi][0][1], af[mi][0][2], af[mi][0][3], bl[0], bl[1]);
                    MMA16816(acc[mi][2 * p], af[mi][1][0], af[mi][1][1], af[mi][1][2], af[mi][1][3], bh[0], bh[1]);
                    // n-tile 2p+1
                    MMA16816(acc[mi][2 * p + 1], af[mi][0][0], af[mi][0][1], af[mi][0][2], af[mi][0][3], bh[2], bh[3]);
                    MMA16816(acc[mi][2 * p + 1], af[mi][0][0], af[mi][0][1], af[mi][0][2], af[mi][0][3], bl[2], bl[3]);
                    MMA16816(acc[mi][2 * p + 1], af[mi][1][0], af[mi][1][1], af[mi][1][2], af[mi][1][3], bh[2], bh[3]);
                }
            }
        }
        __syncthreads();
    }

    // ---- epilogue ----
    float s = 0.f, oms = 0.f;
    const float* X = 0;
    if (epi) {
        float sv = *skipp;
        s = 1.f / (1.f + expf(-sv));
        oms = 1.f - s;
        X = sel_buf(x_sel) + x_off;
    }
#pragma unroll
    for (int mi = 0; mi < 4; mi++) {
#pragma unroll
        for (int nj = 0; nj < 4; nj++) {
            int rbase = bm + wm + mi * 16 + (lane >> 2);
            int col = bn + wn + nj * 8 + (lane & 3) * 2;
            float2 b2 = *(const float2*)&bias[col];
#pragma unroll
            for (int h = 0; h < 2; h++) {
                int gr = rbase + h * 8;
                if (gr >= M) continue;
                float o0 = acc[mi][nj][h * 2 + 0] + b2.x;
                float o1 = acc[mi][nj][h * 2 + 1] + b2.y;
                if (!epi) {
                    *(float2*)&C[(long)gr * N + col] = make_float2(o0, o1);
                } else {
                    float2 xv = *(const float2*)&X[(long)gr * 128 + col];
                    float n0 = s * o0 + oms * xv.x;
                    float n1 = s * o1 + oms * xv.y;
                    *(float2*)&C[(long)gr * N + col] =
                        make_float2(fmaxf(n0, 0.f) + xv.x, fmaxf(n1, 0.f) + xv.y);
                }
            }
        }
    }
}

// ---------------- edge-phase kernels (unchanged) ----------------

__global__ __launch_bounds__(256)
void krvr_kernel(const float* __restrict__ Ak, const float* __restrict__ Av,
                 int l, int r, int st_off, int nsrc, int kroff) {
    __shared__ float sA[2][HH][DD][DD];
    int tid = threadIdx.x;
    const float* Akb = Ak + (long)(l * NREL + r) * HH * DD * DD;
    const float* Avb = Av + (long)(l * NREL + r) * HH * DD * DD;
    float* sflat = &sA[0][0][0][0];
    for (int i = tid; i < 2048; i += 256) {
        sflat[i] = Akb[i];
        sflat[2048 + i] = Avb[i];
    }
    __syncthreads();

    int half = tid >> 7;
    int h = (tid & 127) >> 4;
    int e = tid & 15;
    int n0 = blockIdx.x * 16;
    float* dst = half ? g_vr : g_kr;
    int kqv_off = half ? 256 : 0;

    for (int ni = 0; ni < 16; ni++) {
        int n = n0 + ni;
        if (n >= nsrc) break;
        const float* srcp = g_kqv + (long)(st_off + n) * F3 + kqv_off + h * DD;
        float acc = 0.f;
#pragma unroll
        for (int d = 0; d < DD; d++) acc += srcp[d] * sA[half][h][d][e];
        dst[(long)(kroff + n) * FF + h * DD + e] = acc;
    }
}

__global__ __launch_bounds__(256)
void alpha_kernel(const int* __restrict__ src, const int* __restrict__ dst,
                  const float* __restrict__ prel,
                  int E, int l, int r, int dt_off, int kroff, int ebase) {
    int warp = (blockIdx.x * blockDim.x + threadIdx.x) >> 5;
    int lane = threadIdx.x & 31;
    if (warp >= E) return;
    int sn = src[warp], dn = dst[warp];
    float4 q4 = *(const float4*)(g_kqv + (long)(dt_off + dn) * F3 + FF + lane * 4);
    float4 k4 = *(const float4*)(g_kr + (long)(kroff + sn) * FF + lane * 4);
    float p = q4.x * k4.x + q4.y * k4.y + q4.z * k4.z + q4.w * k4.w;
    p += __shfl_xor_sync(0xFFFFFFFFu, p, 1);
    p += __shfl_xor_sync(0xFFFFFFFFu, p, 2);
    if ((lane & 3) == 0) {
        int h = lane >> 2;
        float a = p * prel[(l * NREL + r) * HH + h] * 0.25f;
        float ex = expf(a);
        g_alpha[(long)(ebase + warp) * HH + h] = ex;
        atomicAdd(&g_denom[(long)(dt_off + dn) * HH + h], ex);
    }
}

__global__ __launch_bounds__(256)
void agg_kernel(const int* __restrict__ src, const int* __restrict__ dst,
                int E, int dt_off, int kroff, int ebase) {
    int warp = (blockIdx.x * blockDim.x + threadIdx.x) >> 5;
    int lane = threadIdx.x & 31;
    if (warp >= E) return;
    int sn = src[warp], dn = dst[warp];
    int h = lane >> 2;
    long nb = (long)(dt_off + dn) * HH + h;
    float ex  = g_alpha[(long)(ebase + warp) * HH + h];
    float den = g_denom[nb];
    float w = ex / den;
    float4 v4 = *(const float4*)(g_vr + (long)(kroff + sn) * FF + lane * 4);
    float* o = g_agg + (long)(dt_off + dn) * FF + lane * 4;
    asm volatile("red.global.add.v4.f32 [%0], {%1,%2,%3,%4};"
                 :: "l"(o), "f"(v4.x * w), "f"(v4.y * w),
                    "f"(v4.z * w), "f"(v4.w * w)
                 : "memory");
}

// ---------------- launch ----------------
extern "C" void kernel_launch(void* const* d_in, const int* in_sizes, int n_in,
                              void* d_out, int out_size) {
    const float* xg   = (const float*)d_in[0];
    const float* xd   = (const float*)d_in[1];
    const float* xr   = (const float*)d_in[2];
    const float* Wkqv = (const float*)d_in[3];
    const float* bkqv = (const float*)d_in[4];
    const float* Ak   = (const float*)d_in[5];
    const float* Av   = (const float*)d_in[6];
    const float* prel = (const float*)d_in[7];
    const float* Wout = (const float*)d_in[8];
    const float* bout = (const float*)d_in[9];
    const float* skip = (const float*)d_in[10];
    const int* ei[4] = {(const int*)d_in[11], (const int*)d_in[12],
                        (const int*)d_in[13], (const int*)d_in[14]};
    float* outp = (float*)d_out;

    const int NELEM_BLOCKS = (NTOT * FF + 255) / 256;
    const int SPLIT_BLOCKS = (NTOT * FF / 8 + 255) / 256;

    copyin_kernel<<<NELEM_BLOCKS, 256>>>(xg, xd, xr);
    splitw_kernel<<<(WTOT + 255) / 256, 256>>>(Wkqv, Wout);

    for (int l = 0; l < NLAYER; l++) {
        int a_x = (l == 0) ? 0 : 1;

        // 1) split x into bf16 planes
        split_kernel<<<SPLIT_BLOCKS, 256>>>(a_x, 0);

        // 2) kqv = x @ Wkqv + bkqv (tensor cores)
        for (int t = 0; t < NTYPE; t++) {
            dim3 grid(F3 / 128, (h_NS[t] + 127) / 128);
            mma_gemm<<<grid, 256>>>(
                (long)h_OFFS[t],
                (long)(l * NTYPE + t) * F3 * FF,
                bkqv + (long)(l * NTYPE + t) * F3,
                3 /*g_kqv*/, 0, (long)h_OFFS[t] * F3,
                h_NS[t], F3, 0, 0, 0, 0);
        }

        // 3) reset softmax/aggregation state
        init_kernel<<<NELEM_BLOCKS, 256>>>();

        // 4) relation-specific k_r, v_r
        for (int r = 0; r < NREL; r++) {
            int st = h_SRCT[r];
            krvr_kernel<<<(h_NS[st] + 15) / 16, 256>>>(
                Ak, Av, l, r, h_OFFS[st], h_NS[st], h_KROFF[r]);
        }

        // 5) edge logits + exp + denominator
        for (int r = 0; r < NREL; r++) {
            int E = h_ES[r];
            alpha_kernel<<<(E * 32 + 255) / 256, 256>>>(
                ei[r], ei[r] + E, prel, E, l, r,
                h_OFFS[h_DSTT[r]], h_KROFF[r], h_EBASE[r]);
        }

        // 6) weighted scatter-add of v_r
        for (int r = 0; r < NREL; r++) {
            int E = h_ES[r];
            agg_kernel<<<(E * 32 + 255) / 256, 256>>>(
                ei[r], ei[r] + E, E,
                h_OFFS[h_DSTT[r]], h_KROFF[r], h_EBASE[r]);
        }

        // 7) split gelu(agg) into bf16 planes
        split_kernel<<<SPLIT_BLOCKS, 256>>>(2, 1);

        // 8) out GEMM + skip-blend + relu + residual
        for (int t = 0; t < NTYPE; t++) {
            dim3 grid(FF / 128, (h_NS[t] + 127) / 128);
            int c_sel = (l == 0) ? 1 : -1;
            mma_gemm<<<grid, 256>>>(
                (long)h_OFFS[t],
                (long)KQVW_ELEMS + (long)(l * NTYPE + t) * FF * FF,
                bout + (long)(l * NTYPE + t) * FF,
                c_sel, outp, (long)h_OFFS[t] * FF,
                h_NS[t], FF, 1,
                a_x, (long)h_OFFS[t] * FF,
                skip + l * NTYPE + t);
        }
    }
    (void)in_sizes; (void)n_in; (void)out_size;
}